// round 3
// baseline (speedup 1.0000x reference)
#include <cuda_runtime.h>

// Problem constants
#define T_   4
#define B_   2
#define C_   384
#define L_   1024
#define H_   8
#define D_   48
#define C2_  768
#define BH_  16            // B_*H_
#define BCL  (B_*C_*L_)    // 786432
#define LL   (L_*L_)       // 1048576

// Scratch (device globals)
__device__ float         g_xs [T_*BCL];          // spikes of x (float 0/1)
__device__ float         g_y  [T_*B_*C2_*L_];    // bn1(W_w @ xs)
__device__ unsigned char g_spk[T_*BH_*LL];       // attn spikes (uint8)
__device__ float         g_o1 [T_*BCL];          // y2 @ spk, then spikes in place

typedef unsigned long long u64;

// ---- packed f32x2 helpers (2x fp32 FMA throughput on sm_103a) ----
__device__ __forceinline__ u64 pk2(float lo, float hi) {
    u64 r; asm("mov.b64 %0,{%1,%2};" : "=l"(r) : "f"(lo), "f"(hi)); return r;
}
__device__ __forceinline__ void upk2(float& lo, float& hi, u64 v) {
    asm("mov.b64 {%0,%1},%2;" : "=f"(lo), "=f"(hi) : "l"(v));
}
__device__ __forceinline__ void ffma2(u64& d, u64 a, u64 b) {
    asm("fma.rn.f32x2 %0,%1,%2,%0;" : "+l"(d) : "l"(a), "l"(b));
}

// ---------------------------------------------------------------------------
// K1: membrane scan over x -> binary spikes xs (float 0/1)
// ---------------------------------------------------------------------------
__global__ __launch_bounds__(256) void k_scan_x(const float* __restrict__ x) {
    int i = blockIdx.x * 256 + threadIdx.x;
    if (i >= BCL) return;
    float mem = 0.f, sp = 0.f;
#pragma unroll
    for (int t = 0; t < T_; ++t) {
        mem = mem * 0.25f * (1.f - sp) + x[(size_t)t * BCL + i];
        sp  = (mem > 0.5f) ? 1.f : 0.f;
        g_xs[(size_t)t * BCL + i] = sp;
    }
}

// ---------------------------------------------------------------------------
// K2 / K6: batched GEMM Y[tb] = bn(W @ X[tb]) (+ residual)
//   Block tile 64M x 128N, thread tile 8M x 4N (2 f32x2 accs per row).
//   Warp w owns rows m0+w*8.. (A loads are warp-broadcast); lane owns n=lane*4.
// ---------------------------------------------------------------------------
__global__ __launch_bounds__(256) void k_gemm_bn(
    const float* __restrict__ W,
    const float* __restrict__ gamma, const float* __restrict__ beta,
    const float* __restrict__ mean,  const float* __restrict__ var,
    const float* __restrict__ resid,
    float* __restrict__ outExt, int M, int which)
{
    const float* Xb = (which == 0) ? g_xs : g_o1;
    float*       Yb = (which == 0) ? g_y  : outExt;

    const int tid  = threadIdx.x;
    const int lane = tid & 31, w = tid >> 5;
    const int n0 = blockIdx.x * 128;
    const int m0 = blockIdx.y * 64;
    const int tb = blockIdx.z;

    const float* X = Xb + (size_t)tb * (C_ * L_);
    float*       Y = Yb + (size_t)tb * (size_t)M * L_;

    __shared__ float As[16][68];   // padded: kills STS bank conflicts, keeps 16B align
    __shared__ float Bs[16][128];

    u64 acc[8][2];
#pragma unroll
    for (int i = 0; i < 8; ++i) { acc[i][0] = 0ull; acc[i][1] = 0ull; }

    const int am = tid >> 2, ak = (tid & 3) * 4;    // A fill: W[m][k..k+3]
    const int bk = tid >> 4, bn = (tid & 15) * 8;   // B fill: 2 float4 per thread

    for (int kt = 0; kt < C_; kt += 16) {
        float4 av = *(const float4*)(W + (size_t)(m0 + am) * C_ + kt + ak);
        As[ak + 0][am] = av.x; As[ak + 1][am] = av.y;
        As[ak + 2][am] = av.z; As[ak + 3][am] = av.w;
        *(float4*)&Bs[bk][bn]     = *(const float4*)(X + (size_t)(kt + bk) * L_ + n0 + bn);
        *(float4*)&Bs[bk][bn + 4] = *(const float4*)(X + (size_t)(kt + bk) * L_ + n0 + bn + 4);
        __syncthreads();
#pragma unroll
        for (int k = 0; k < 16; ++k) {
            float4 bv = *(const float4*)&Bs[k][lane * 4];
            u64 b0 = pk2(bv.x, bv.y), b1 = pk2(bv.z, bv.w);
            float4 a0 = *(const float4*)&As[k][w * 8];
            float4 a1 = *(const float4*)&As[k][w * 8 + 4];
            float a[8] = {a0.x, a0.y, a0.z, a0.w, a1.x, a1.y, a1.z, a1.w};
#pragma unroll
            for (int i = 0; i < 8; ++i) {
                u64 s = pk2(a[i], a[i]);
                ffma2(acc[i][0], s, b0);
                ffma2(acc[i][1], s, b1);
            }
        }
        __syncthreads();
    }

#pragma unroll
    for (int i = 0; i < 8; ++i) {
        int m = m0 + w * 8 + i;
        float inv = gamma[m] / sqrtf(var[m] + 1e-5f);
        float off = beta[m] - mean[m] * inv;
        float r0, r1, r2, r3;
        upk2(r0, r1, acc[i][0]); upk2(r2, r3, acc[i][1]);
        float4 r = make_float4(r0 * inv + off, r1 * inv + off,
                               r2 * inv + off, r3 * inv + off);
        if (resid) {
            const float4 rx = *(const float4*)(resid + (size_t)tb * (C_ * L_) +
                                               (size_t)m * L_ + n0 + lane * 4);
            r.x += rx.x; r.y += rx.y; r.z += rx.z; r.w += rx.w;
        }
        *(float4*)(Y + (size_t)m * L_ + n0 + lane * 4) = r;
    }
}

// ---------------------------------------------------------------------------
// K3: fused attn GEMM (K=48) + membrane scan over t -> uint8 spikes.
//   Block tile 64L x 128M, thread tile 8L x 4M. A (y1) is warp-broadcast.
// ---------------------------------------------------------------------------
__global__ __launch_bounds__(256) void k_attn_fused() {
    const int bh = blockIdx.z;
    const int b = bh >> 3, h = bh & 7;
    const int l0 = blockIdx.y * 64;
    const int m0 = blockIdx.x * 128;

    const int tid = threadIdx.x;
    const int lane = tid & 31, w = tid >> 5;

    __shared__ float As[48][64];    // y1[d][l-tile]
    __shared__ float Bs[48][128];   // xr[d][m-tile]

    float mem[8][4];
#pragma unroll
    for (int i = 0; i < 8; ++i)
#pragma unroll
        for (int j = 0; j < 4; ++j) mem[i][j] = 0.f;

    for (int t = 0; t < T_; ++t) {
        const float* y1 = g_y  + ((size_t)(t * B_ + b) * C2_ + h * 96) * L_;
        const float* xr = g_xs + ((size_t)(t * B_ + b) * C_  + h * D_) * L_;
#pragma unroll
        for (int q = 0; q < 3; ++q) {
            int idx = tid + q * 256;            // 0..767
            int d = idx >> 4, lc = (idx & 15) * 4;
            *(float4*)&As[d][lc] = *(const float4*)(y1 + (size_t)d * L_ + l0 + lc);
        }
#pragma unroll
        for (int q = 0; q < 6; ++q) {
            int idx = tid + q * 256;            // 0..1535
            int d = idx >> 5, mc = (idx & 31) * 4;
            *(float4*)&Bs[d][mc] = *(const float4*)(xr + (size_t)d * L_ + m0 + mc);
        }
        __syncthreads();

        u64 acc[8][2];
#pragma unroll
        for (int i = 0; i < 8; ++i) { acc[i][0] = 0ull; acc[i][1] = 0ull; }

#pragma unroll 4
        for (int k = 0; k < 48; ++k) {
            float4 bv = *(const float4*)&Bs[k][lane * 4];
            u64 b0 = pk2(bv.x, bv.y), b1 = pk2(bv.z, bv.w);
            float4 a0 = *(const float4*)&As[k][w * 8];
            float4 a1 = *(const float4*)&As[k][w * 8 + 4];
            float a[8] = {a0.x, a0.y, a0.z, a0.w, a1.x, a1.y, a1.z, a1.w};
#pragma unroll
            for (int i = 0; i < 8; ++i) {
                u64 s = pk2(a[i], a[i]);
                ffma2(acc[i][0], s, b0);
                ffma2(acc[i][1], s, b1);
            }
        }

        unsigned char* o = g_spk + (size_t)(t * BH_ + bh) * LL;
#pragma unroll
        for (int i = 0; i < 8; ++i) {
            float v0, v1, v2, v3;
            upk2(v0, v1, acc[i][0]); upk2(v2, v3, acc[i][1]);
            float* mi = mem[i];
            mi[0] = mi[0] * 0.25f * ((mi[0] > 0.5f) ? 0.f : 1.f) + v0;
            mi[1] = mi[1] * 0.25f * ((mi[1] > 0.5f) ? 0.f : 1.f) + v1;
            mi[2] = mi[2] * 0.25f * ((mi[2] > 0.5f) ? 0.f : 1.f) + v2;
            mi[3] = mi[3] * 0.25f * ((mi[3] > 0.5f) ? 0.f : 1.f) + v3;
            uchar4 s;
            s.x = (mi[0] > 0.5f) ? 1 : 0;
            s.y = (mi[1] > 0.5f) ? 1 : 0;
            s.z = (mi[2] > 0.5f) ? 1 : 0;
            s.w = (mi[3] > 0.5f) ? 1 : 0;
            *(uchar4*)(o + (size_t)(l0 + w * 8 + i) * L_ + m0 + lane * 4) = s;
        }
        __syncthreads();
    }
}

// ---------------------------------------------------------------------------
// K4: out1[d,m] = sum_l y2[d,l] * spk[l,m]   (M=48, N=1024 tiled 256, K=1024)
//   Block tile 48M x 256N, thread tile 6M x 8N (N split in two 128-halves
//   so both B LDS.128 reads are conflict-free). A (y2) is warp-broadcast.
// ---------------------------------------------------------------------------
__global__ __launch_bounds__(256) void k_gemm2() {
    const int z = blockIdx.z;              // t*16 + bh
    const int t = z >> 4, bh = z & 15;
    const int b = bh >> 3, h = bh & 7;

    const float*         y2  = g_y   + ((size_t)(t * B_ + b) * C2_ + h * 96 + 48) * L_;
    const unsigned char* S   = g_spk + (size_t)z * LL;
    float*               out = g_o1  + ((size_t)(t * B_ + b) * C_ + h * D_) * L_;

    const int n0 = blockIdx.x * 256;
    const int tid = threadIdx.x;
    const int lane = tid & 31, w = tid >> 5;

    __shared__ float As[16][50];    // y2^T [k][d], padded (even, conflict-free)
    __shared__ float Bs[16][256];   // spikes as float [k][n]

    u64 acc[6][4];
#pragma unroll
    for (int i = 0; i < 6; ++i)
#pragma unroll
        for (int j = 0; j < 4; ++j) acc[i][j] = 0ull;

    for (int kt = 0; kt < L_; kt += 16) {
#pragma unroll
        for (int q = 0; q < 3; ++q) {
            int idx = tid + q * 256;           // 0..767
            int d = idx >> 4, k = idx & 15;
            As[k][d] = y2[(size_t)d * L_ + kt + k];
        }
#pragma unroll
        for (int q = 0; q < 4; ++q) {
            int idx = tid + q * 256;           // 0..1023
            int k = idx >> 6, c = (idx & 63) * 4;
            uchar4 v = *(const uchar4*)(S + (size_t)(kt + k) * L_ + n0 + c);
            float4 f;
            f.x = v.x ? 1.f : 0.f; f.y = v.y ? 1.f : 0.f;
            f.z = v.z ? 1.f : 0.f; f.w = v.w ? 1.f : 0.f;
            *(float4*)&Bs[k][c] = f;
        }
        __syncthreads();
#pragma unroll
        for (int k = 0; k < 16; ++k) {
            float4 bv0 = *(const float4*)&Bs[k][lane * 4];
            float4 bv1 = *(const float4*)&Bs[k][128 + lane * 4];
            u64 b0 = pk2(bv0.x, bv0.y), b1 = pk2(bv0.z, bv0.w);
            u64 b2 = pk2(bv1.x, bv1.y), b3 = pk2(bv1.z, bv1.w);
            float2 a01 = *(const float2*)&As[k][w * 6];
            float2 a23 = *(const float2*)&As[k][w * 6 + 2];
            float2 a45 = *(const float2*)&As[k][w * 6 + 4];
            float a[6] = {a01.x, a01.y, a23.x, a23.y, a45.x, a45.y};
#pragma unroll
            for (int i = 0; i < 6; ++i) {
                u64 s = pk2(a[i], a[i]);
                ffma2(acc[i][0], s, b0);
                ffma2(acc[i][1], s, b1);
                ffma2(acc[i][2], s, b2);
                ffma2(acc[i][3], s, b3);
            }
        }
        __syncthreads();
    }

#pragma unroll
    for (int i = 0; i < 6; ++i) {
        int d = w * 6 + i;
        float r0, r1, r2, r3;
        upk2(r0, r1, acc[i][0]); upk2(r2, r3, acc[i][1]);
        *(float4*)(out + (size_t)d * L_ + n0 + lane * 4) = make_float4(r0, r1, r2, r3);
        upk2(r0, r1, acc[i][2]); upk2(r2, r3, acc[i][3]);
        *(float4*)(out + (size_t)d * L_ + n0 + 128 + lane * 4) = make_float4(r0, r1, r2, r3);
    }
}

// ---------------------------------------------------------------------------
// K5: membrane scan over out1 (in-place -> binary spikes)
// ---------------------------------------------------------------------------
__global__ __launch_bounds__(256) void k_scan_o1() {
    int i = blockIdx.x * 256 + threadIdx.x;
    if (i >= BCL) return;
    float mem = 0.f, sp = 0.f;
#pragma unroll
    for (int t = 0; t < T_; ++t) {
        mem = mem * 0.25f * (1.f - sp) + g_o1[(size_t)t * BCL + i];
        sp  = (mem > 0.5f) ? 1.f : 0.f;
        g_o1[(size_t)t * BCL + i] = sp;
    }
}

// ---------------------------------------------------------------------------
extern "C" void kernel_launch(void* const* d_in, const int* in_sizes, int n_in,
                              void* d_out, int out_size) {
    (void)in_sizes; (void)n_in; (void)out_size;
    const float* x   = (const float*)d_in[0];
    const float* W_w = (const float*)d_in[1];
    const float* g1  = (const float*)d_in[2];
    const float* be1 = (const float*)d_in[3];
    const float* me1 = (const float*)d_in[4];
    const float* v1  = (const float*)d_in[5];
    const float* pw  = (const float*)d_in[6];
    const float* g2  = (const float*)d_in[7];
    const float* be2 = (const float*)d_in[8];
    const float* me2 = (const float*)d_in[9];
    const float* v2  = (const float*)d_in[10];
    float* out = (float*)d_out;

    k_scan_x<<<BCL / 256, 256>>>(x);
    k_gemm_bn<<<dim3(L_ / 128, C2_ / 64, T_ * B_), 256>>>(
        W_w, g1, be1, me1, v1, nullptr, nullptr, C2_, 0);
    k_attn_fused<<<dim3(L_ / 128, L_ / 64, BH_), 256>>>();
    k_gemm2<<<dim3(L_ / 256, 1, T_ * BH_), 256>>>();
    k_scan_o1<<<BCL / 256, 256>>>();
    k_gemm_bn<<<dim3(L_ / 128, C_ / 64, T_ * B_), 256>>>(
        pw, g2, be2, me2, v2, x, out, C_, 1);
}

// round 5
// speedup vs baseline: 1.1691x; 1.1691x over previous
#include <cuda_runtime.h>
#include <cuda_bf16.h>

// Problem constants
#define T_   4
#define B_   2
#define C_   384
#define L_   1024
#define H_   8
#define D_   48
#define C2_  768
#define BH_  16            // B_*H_
#define BCL  (B_*C_*L_)    // 786432
#define LL   (L_*L_)       // 1048576

// Scratch (device globals)
__device__ float         g_xs  [T_*BCL];            // spikes of x (float 0/1)
__device__ float         g_y   [T_*B_*C2_*L_];      // bn1(W_w @ xs)
__device__ __nv_bfloat16 g_spkT[T_*BH_*LL];         // attn spikes bf16, [z][m][l]
__device__ __nv_bfloat16 g_y2s [T_*B_*H_*3*64*L_];  // y2 3-split bf16 [t2b][h][s][64][l]
__device__ float         g_o1  [T_*BCL];            // out1 (then spikes in place)

typedef unsigned long long u64;

// ---- packed f32x2 helpers ----
__device__ __forceinline__ u64 pk2(float lo, float hi) {
    u64 r; asm("mov.b64 %0,{%1,%2};" : "=l"(r) : "f"(lo), "f"(hi)); return r;
}
__device__ __forceinline__ void upk2(float& lo, float& hi, u64 v) {
    asm("mov.b64 {%0,%1},%2;" : "=f"(lo), "=f"(hi) : "l"(v));
}
__device__ __forceinline__ void ffma2(u64& d, u64 a, u64 b) {
    asm("fma.rn.f32x2 %0,%1,%2,%0;" : "+l"(d) : "l"(a), "l"(b));
}

// ---- mma.sync / ldmatrix helpers (compute_103-safe, sm_80+ features) ----
__device__ __forceinline__ unsigned smem_u32(const void* p) {
    unsigned r;
    asm("{ .reg .u64 t; cvta.to.shared.u64 t, %1; cvt.u32.u64 %0, t; }" : "=r"(r) : "l"(p));
    return r;
}
__device__ __forceinline__ void ldsm_x4(unsigned* r, unsigned addr) {
    asm volatile("ldmatrix.sync.aligned.m8n8.x4.shared.b16 {%0,%1,%2,%3}, [%4];"
                 : "=r"(r[0]), "=r"(r[1]), "=r"(r[2]), "=r"(r[3]) : "r"(addr));
}
__device__ __forceinline__ void ldsm_x2(unsigned* r, unsigned addr) {
    asm volatile("ldmatrix.sync.aligned.m8n8.x2.shared.b16 {%0,%1}, [%2];"
                 : "=r"(r[0]), "=r"(r[1]) : "r"(addr));
}
__device__ __forceinline__ void mma16816(float* d, const unsigned* a, const unsigned* b) {
    asm volatile(
        "mma.sync.aligned.m16n8k16.row.col.f32.bf16.bf16.f32 "
        "{%0,%1,%2,%3},{%4,%5,%6,%7},{%8,%9},{%0,%1,%2,%3};"
        : "+f"(d[0]), "+f"(d[1]), "+f"(d[2]), "+f"(d[3])
        : "r"(a[0]), "r"(a[1]), "r"(a[2]), "r"(a[3]), "r"(b[0]), "r"(b[1]));
}

// ---------------------------------------------------------------------------
// K1: membrane scan over x -> binary spikes xs (float 0/1)
// ---------------------------------------------------------------------------
__global__ __launch_bounds__(256) void k_scan_x(const float* __restrict__ x) {
    int i = blockIdx.x * 256 + threadIdx.x;
    if (i >= BCL) return;
    float mem = 0.f, sp = 0.f;
#pragma unroll
    for (int t = 0; t < T_; ++t) {
        mem = mem * 0.25f * (1.f - sp) + x[(size_t)t * BCL + i];
        sp  = (mem > 0.5f) ? 1.f : 0.f;
        g_xs[(size_t)t * BCL + i] = sp;
    }
}

// ---------------------------------------------------------------------------
// K2 / K6: batched GEMM Y[tb] = bn(W @ X[tb]) (+ residual)  (f32x2 path)
// ---------------------------------------------------------------------------
__global__ __launch_bounds__(256) void k_gemm_bn(
    const float* __restrict__ W,
    const float* __restrict__ gamma, const float* __restrict__ beta,
    const float* __restrict__ mean,  const float* __restrict__ var,
    const float* __restrict__ resid,
    float* __restrict__ outExt, int M, int which)
{
    const float* Xb = (which == 0) ? g_xs : g_o1;
    float*       Yb = (which == 0) ? g_y  : outExt;

    const int tid  = threadIdx.x;
    const int lane = tid & 31, w = tid >> 5;
    const int n0 = blockIdx.x * 128;
    const int m0 = blockIdx.y * 64;
    const int tb = blockIdx.z;

    const float* X = Xb + (size_t)tb * (C_ * L_);
    float*       Y = Yb + (size_t)tb * (size_t)M * L_;

    __shared__ float As[16][68];
    __shared__ float Bs[16][128];

    u64 acc[8][2];
#pragma unroll
    for (int i = 0; i < 8; ++i) { acc[i][0] = 0ull; acc[i][1] = 0ull; }

    const int am = tid >> 2, ak = (tid & 3) * 4;
    const int bk = tid >> 4, bn = (tid & 15) * 8;

    for (int kt = 0; kt < C_; kt += 16) {
        float4 av = *(const float4*)(W + (size_t)(m0 + am) * C_ + kt + ak);
        As[ak + 0][am] = av.x; As[ak + 1][am] = av.y;
        As[ak + 2][am] = av.z; As[ak + 3][am] = av.w;
        *(float4*)&Bs[bk][bn]     = *(const float4*)(X + (size_t)(kt + bk) * L_ + n0 + bn);
        *(float4*)&Bs[bk][bn + 4] = *(const float4*)(X + (size_t)(kt + bk) * L_ + n0 + bn + 4);
        __syncthreads();
#pragma unroll
        for (int k = 0; k < 16; ++k) {
            float4 bv = *(const float4*)&Bs[k][lane * 4];
            u64 b0 = pk2(bv.x, bv.y), b1 = pk2(bv.z, bv.w);
            float4 a0 = *(const float4*)&As[k][w * 8];
            float4 a1 = *(const float4*)&As[k][w * 8 + 4];
            float a[8] = {a0.x, a0.y, a0.z, a0.w, a1.x, a1.y, a1.z, a1.w};
#pragma unroll
            for (int i = 0; i < 8; ++i) {
                u64 s = pk2(a[i], a[i]);
                ffma2(acc[i][0], s, b0);
                ffma2(acc[i][1], s, b1);
            }
        }
        __syncthreads();
    }

#pragma unroll
    for (int i = 0; i < 8; ++i) {
        int m = m0 + w * 8 + i;
        float inv = gamma[m] / sqrtf(var[m] + 1e-5f);
        float off = beta[m] - mean[m] * inv;
        float r0, r1, r2, r3;
        upk2(r0, r1, acc[i][0]); upk2(r2, r3, acc[i][1]);
        float4 r = make_float4(r0 * inv + off, r1 * inv + off,
                               r2 * inv + off, r3 * inv + off);
        if (resid) {
            const float4 rx = *(const float4*)(resid + (size_t)tb * (C_ * L_) +
                                               (size_t)m * L_ + n0 + lane * 4);
            r.x += rx.x; r.y += rx.y; r.z += rx.z; r.w += rx.w;
        }
        *(float4*)(Y + (size_t)m * L_ + n0 + lane * 4) = r;
    }
}

// ---------------------------------------------------------------------------
// K2b: split y2 (fp32) into 3 exact bf16 parts, zero-padded to 64 d-rows.
//   g_y2s[t2b][h][s][64][1024]
// ---------------------------------------------------------------------------
__global__ __launch_bounds__(256) void k_split_y2() {
    int idx = blockIdx.x * 256 + threadIdx.x;    // 8*8*64*1024 = 2^22
    int l   = idx & 1023;
    int d   = (idx >> 10) & 63;
    int h   = (idx >> 16) & 7;
    int t2b = idx >> 19;
    float v = 0.f;
    if (d < 48)
        v = g_y[(size_t)t2b * C2_ * L_ + (size_t)(h * 96 + 48 + d) * L_ + l];
    __nv_bfloat16 b0 = __float2bfloat16(v);
    float r = v - __bfloat162float(b0);
    __nv_bfloat16 b1 = __float2bfloat16(r);
    r -= __bfloat162float(b1);
    __nv_bfloat16 b2 = __float2bfloat16(r);
    size_t base = (size_t)(t2b * 8 + h) * 3 * 65536 + (size_t)d * 1024 + l;
    g_y2s[base]          = b0;
    g_y2s[base + 65536]  = b1;
    g_y2s[base + 131072] = b2;
}

// ---------------------------------------------------------------------------
// K3: fused attn GEMM (K=48) + membrane scan over t -> bf16 spikes, TRANSPOSED
//   computes attnT[m][l] = sum_d xr[d][m]*y1[d][l]; writes g_spkT[z][m][l].
// ---------------------------------------------------------------------------
__global__ __launch_bounds__(256) void k_attn_fused() {
    const int bh = blockIdx.z;
    const int b = bh >> 3, h = bh & 7;
    const int m0 = blockIdx.y * 64;
    const int l0 = blockIdx.x * 128;

    const int tid = threadIdx.x;
    const int lane = tid & 31, w = tid >> 5;

    __shared__ float As[48][64];    // xr[d][m-tile]
    __shared__ float Bs[48][128];   // y1[d][l-tile]

    float mem[8][4];
#pragma unroll
    for (int i = 0; i < 8; ++i)
#pragma unroll
        for (int j = 0; j < 4; ++j) mem[i][j] = 0.f;

    for (int t = 0; t < T_; ++t) {
        const float* y1 = g_y  + ((size_t)(t * B_ + b) * C2_ + h * 96) * L_;
        const float* xr = g_xs + ((size_t)(t * B_ + b) * C_  + h * D_) * L_;
#pragma unroll
        for (int q = 0; q < 3; ++q) {
            int idx = tid + q * 256;            // 0..767
            int d = idx >> 4, mc = (idx & 15) * 4;
            *(float4*)&As[d][mc] = *(const float4*)(xr + (size_t)d * L_ + m0 + mc);
        }
#pragma unroll
        for (int q = 0; q < 6; ++q) {
            int idx = tid + q * 256;            // 0..1535
            int d = idx >> 5, lc = (idx & 31) * 4;
            *(float4*)&Bs[d][lc] = *(const float4*)(y1 + (size_t)d * L_ + l0 + lc);
        }
        __syncthreads();

        u64 acc[8][2];
#pragma unroll
        for (int i = 0; i < 8; ++i) { acc[i][0] = 0ull; acc[i][1] = 0ull; }

#pragma unroll 4
        for (int k = 0; k < 48; ++k) {
            float4 bv = *(const float4*)&Bs[k][lane * 4];
            u64 b0 = pk2(bv.x, bv.y), b1 = pk2(bv.z, bv.w);
            float4 a0 = *(const float4*)&As[k][w * 8];
            float4 a1 = *(const float4*)&As[k][w * 8 + 4];
            float a[8] = {a0.x, a0.y, a0.z, a0.w, a1.x, a1.y, a1.z, a1.w};
#pragma unroll
            for (int i = 0; i < 8; ++i) {
                u64 s = pk2(a[i], a[i]);
                ffma2(acc[i][0], s, b0);
                ffma2(acc[i][1], s, b1);
            }
        }

        __nv_bfloat16* o = g_spkT + (size_t)(t * BH_ + bh) * LL;
#pragma unroll
        for (int i = 0; i < 8; ++i) {
            float v0, v1, v2, v3;
            upk2(v0, v1, acc[i][0]); upk2(v2, v3, acc[i][1]);
            float* mi = mem[i];
            mi[0] = mi[0] * 0.25f * ((mi[0] > 0.5f) ? 0.f : 1.f) + v0;
            mi[1] = mi[1] * 0.25f * ((mi[1] > 0.5f) ? 0.f : 1.f) + v1;
            mi[2] = mi[2] * 0.25f * ((mi[2] > 0.5f) ? 0.f : 1.f) + v2;
            mi[3] = mi[3] * 0.25f * ((mi[3] > 0.5f) ? 0.f : 1.f) + v3;
            ushort4 s;                                  // bf16(1.0) = 0x3F80
            s.x = (mi[0] > 0.5f) ? 0x3F80 : 0;
            s.y = (mi[1] > 0.5f) ? 0x3F80 : 0;
            s.z = (mi[2] > 0.5f) ? 0x3F80 : 0;
            s.w = (mi[3] > 0.5f) ? 0x3F80 : 0;
            *(ushort4*)(o + (size_t)(m0 + w * 8 + i) * L_ + l0 + lane * 4) = s;
        }
        __syncthreads();
    }
}

// ---------------------------------------------------------------------------
// K4: mma.sync GEMM  D[m][d] = sum_{s,l} spkT[m,l] * y2s[s][d][l]
//   Block 128M x 48N, 8 warps (4M x 2N), warp tile 32M x 24N.
//   K-chunks of 64; smem rows padded to 72 bf16 (conflict-free ldmatrix).
// ---------------------------------------------------------------------------
#define PAD_ 72
__global__ __launch_bounds__(256) void k_gemm2_mma() {
    const int z  = blockIdx.y;                 // t*16 + bh
    const int m0 = blockIdx.x * 128;
    const int t = z >> 4, bh = z & 15, b = bh >> 3, h = bh & 7;
    const int t2b = t * 2 + b;

    const int tid = threadIdx.x, lane = tid & 31, wid = tid >> 5;
    const int wm = wid & 3, wn = wid >> 2;     // 4M x 2N warp grid

    __shared__ __nv_bfloat16 As[128 * PAD_];   // 18 KB
    __shared__ __nv_bfloat16 Bs[144 * PAD_];   // 3 splits x 48 rows, 20.25 KB

    const __nv_bfloat16* Ag = g_spkT + (size_t)z * LL + (size_t)m0 * L_;
    const __nv_bfloat16* Bg = g_y2s + (size_t)(t2b * 8 + h) * 3 * 65536;

    float acc[2][3][4] = {};
    const unsigned sA = smem_u32(As), sB = smem_u32(Bs);

    const int al_row  = wm * 32 + (lane & 15);   // + mi*16
    const int al_coff = (lane >> 4) * 8;         // + kk*16
    const int l4 = lane & 15;
    const int bl_row  = wn * 24 + (l4 & 7);      // + s*48 + ni*8
    const int bl_coff = (l4 >> 3) * 8;           // + kk*16

    for (int it = 0; it < 16; ++it) {
        const int kt = it * 64;
        __syncthreads();
#pragma unroll
        for (int q = 0; q < 4; ++q) {            // A: 128 rows x 8 uint4
            int id = tid + q * 256, r = id >> 3, c = id & 7;
            *(uint4*)&As[r * PAD_ + c * 8] =
                *(const uint4*)(Ag + (size_t)r * L_ + kt + c * 8);
        }
#pragma unroll
        for (int q = 0; q < 5; ++q) {            // B: 3 x 48 rows x 8 uint4 = 1152
            int id = tid + q * 256;
            if (id < 1152) {
                int s = id / 384, rr = (id % 384) >> 3, c = id & 7;
                *(uint4*)&Bs[(s * 48 + rr) * PAD_ + c * 8] =
                    *(const uint4*)(Bg + (size_t)s * 65536 + (size_t)rr * 1024 + kt + c * 8);
            }
        }
        __syncthreads();

        unsigned a[4][2][4];
#pragma unroll
        for (int kk = 0; kk < 4; ++kk)
#pragma unroll
            for (int mi = 0; mi < 2; ++mi)
                ldsm_x4(a[kk][mi],
                        sA + 2u * ((al_row + mi * 16) * PAD_ + kk * 16 + al_coff));
#pragma unroll
        for (int s = 0; s < 3; ++s) {
#pragma unroll
            for (int kk = 0; kk < 4; ++kk) {
                unsigned bf[3][2];
#pragma unroll
                for (int ni = 0; ni < 3; ++ni)
                    ldsm_x2(bf[ni],
                            sB + 2u * ((s * 48 + bl_row + ni * 8) * PAD_ + kk * 16 + bl_coff));
#pragma unroll
                for (int mi = 0; mi < 2; ++mi)
#pragma unroll
                    for (int ni = 0; ni < 3; ++ni)
                        mma16816(acc[mi][ni], a[kk][mi], bf[ni]);
            }
        }
    }

    // Epilogue: D[m][d] fragments -> g_o1 [d][m] layout
    float* O = g_o1 + (size_t)t2b * (C_ * L_) + (size_t)(h * D_) * L_;
    const int g = lane >> 2, tig = lane & 3;
#pragma unroll
    for (int mi = 0; mi < 2; ++mi) {
        int m = m0 + wm * 32 + mi * 16 + g;
#pragma unroll
        for (int ni = 0; ni < 3; ++ni) {
            int d0 = wn * 24 + ni * 8 + tig * 2;
            O[(size_t)d0 * L_ + m]             = acc[mi][ni][0];
            O[(size_t)(d0 + 1) * L_ + m]       = acc[mi][ni][1];
            O[(size_t)d0 * L_ + m + 8]         = acc[mi][ni][2];
            O[(size_t)(d0 + 1) * L_ + m + 8]   = acc[mi][ni][3];
        }
    }
}

// ---------------------------------------------------------------------------
// K5: membrane scan over out1 (in-place -> binary spikes)
// ---------------------------------------------------------------------------
__global__ __launch_bounds__(256) void k_scan_o1() {
    int i = blockIdx.x * 256 + threadIdx.x;
    if (i >= BCL) return;
    float mem = 0.f, sp = 0.f;
#pragma unroll
    for (int t = 0; t < T_; ++t) {
        mem = mem * 0.25f * (1.f - sp) + g_o1[(size_t)t * BCL + i];
        sp  = (mem > 0.5f) ? 1.f : 0.f;
        g_o1[(size_t)t * BCL + i] = sp;
    }
}

// ---------------------------------------------------------------------------
extern "C" void kernel_launch(void* const* d_in, const int* in_sizes, int n_in,
                              void* d_out, int out_size) {
    (void)in_sizes; (void)n_in; (void)out_size;
    const float* x   = (const float*)d_in[0];
    const float* W_w = (const float*)d_in[1];
    const float* g1  = (const float*)d_in[2];
    const float* be1 = (const float*)d_in[3];
    const float* me1 = (const float*)d_in[4];
    const float* v1  = (const float*)d_in[5];
    const float* pw  = (const float*)d_in[6];
    const float* g2  = (const float*)d_in[7];
    const float* be2 = (const float*)d_in[8];
    const float* me2 = (const float*)d_in[9];
    const float* v2  = (const float*)d_in[10];
    float* out = (float*)d_out;

    k_scan_x<<<BCL / 256, 256>>>(x);
    k_gemm_bn<<<dim3(L_ / 128, C2_ / 64, T_ * B_), 256>>>(
        W_w, g1, be1, me1, v1, nullptr, nullptr, C2_, 0);
    k_split_y2<<<(8 * 8 * 64 * 1024) / 256, 256>>>();
    k_attn_fused<<<dim3(L_ / 128, L_ / 64, BH_), 256>>>();
    k_gemm2_mma<<<dim3(L_ / 128, T_ * BH_), 256>>>();
    k_scan_o1<<<BCL / 256, 256>>>();
    k_gemm_bn<<<dim3(L_ / 128, C_ / 64, T_ * B_), 256>>>(
        pw, g2, be2, me2, v2, x, out, C_, 1);
}

// round 6
// speedup vs baseline: 1.7539x; 1.5001x over previous
#include <cuda_runtime.h>
#include <cuda_bf16.h>

// Problem constants
#define T_   4
#define B_   2
#define C_   384
#define L_   1024
#define H_   8
#define D_   48
#define C2_  768
#define BH_  16            // B_*H_
#define BCL  (B_*C_*L_)    // 786432
#define LL   (L_*L_)       // 1048576

typedef unsigned long long u64;
typedef unsigned short u16;

// Scratch (device globals; zero-initialized at module load)
__device__ __nv_bfloat16 g_xsb [T_*BCL];           // x spikes, bf16 {0,1}
__device__ __nv_bfloat16 g_Ws  [3*C2_*C_];         // W_w 3-split
__device__ __nv_bfloat16 g_Pws [3*C_*C_];          // proj_w 3-split
__device__ __nv_bfloat16 g_y1s [8*H_*3*48*L_];     // y1 3-split [t2b][h][s][48][l]
__device__ __nv_bfloat16 g_y2s [8*H_*3*64*L_];     // y2 3-split [t2b][h][s][64][l] (48 used)
__device__ __nv_bfloat16 g_spkT[T_*BH_*LL];        // attn spikes bf16 [z][m][l]
__device__ float         g_o1  [T_*BCL];           // out1 fp32 [c][m]
__device__ __nv_bfloat16 g_o1b [T_*BCL];           // out1 spikes bf16

// ---- mma.sync / ldmatrix helpers (compute_103-safe) ----
__device__ __forceinline__ unsigned smem_u32(const void* p) {
    unsigned r;
    asm("{ .reg .u64 t; cvta.to.shared.u64 t, %1; cvt.u32.u64 %0, t; }" : "=r"(r) : "l"(p));
    return r;
}
__device__ __forceinline__ void ldsm_x4(unsigned* r, unsigned addr) {
    asm volatile("ldmatrix.sync.aligned.m8n8.x4.shared.b16 {%0,%1,%2,%3}, [%4];"
                 : "=r"(r[0]), "=r"(r[1]), "=r"(r[2]), "=r"(r[3]) : "r"(addr));
}
__device__ __forceinline__ void ldsm_x4t(unsigned* r, unsigned addr) {
    asm volatile("ldmatrix.sync.aligned.m8n8.x4.trans.shared.b16 {%0,%1,%2,%3}, [%4];"
                 : "=r"(r[0]), "=r"(r[1]), "=r"(r[2]), "=r"(r[3]) : "r"(addr));
}
__device__ __forceinline__ void ldsm_x2(unsigned* r, unsigned addr) {
    asm volatile("ldmatrix.sync.aligned.m8n8.x2.shared.b16 {%0,%1}, [%2];"
                 : "=r"(r[0]), "=r"(r[1]) : "r"(addr));
}
__device__ __forceinline__ void mma16816(float* d, const unsigned* a, const unsigned* b) {
    asm volatile(
        "mma.sync.aligned.m16n8k16.row.col.f32.bf16.bf16.f32 "
        "{%0,%1,%2,%3},{%4,%5,%6,%7},{%8,%9},{%0,%1,%2,%3};"
        : "+f"(d[0]), "+f"(d[1]), "+f"(d[2]), "+f"(d[3])
        : "r"(a[0]), "r"(a[1]), "r"(a[2]), "r"(a[3]), "r"(b[0]), "r"(b[1]));
}
__device__ __forceinline__ u16 bf_bits(__nv_bfloat16 h) { return *(u16*)&h; }

// ---------------------------------------------------------------------------
// K1: membrane scan over x -> bf16 binary spikes
// ---------------------------------------------------------------------------
__global__ __launch_bounds__(256) void k_scan_x(const float* __restrict__ x) {
    int i = blockIdx.x * 256 + threadIdx.x;
    if (i >= BCL) return;
    float mem = 0.f, sp = 0.f;
#pragma unroll
    for (int t = 0; t < T_; ++t) {
        mem = mem * 0.25f * (1.f - sp) + x[(size_t)t * BCL + i];
        sp  = (mem > 0.5f) ? 1.f : 0.f;
        ((u16*)g_xsb)[(size_t)t * BCL + i] = (mem > 0.5f) ? 0x3F80 : 0;
    }
}

// ---------------------------------------------------------------------------
// K1b: 3-way exact bf16 split of W_w and proj_w
// ---------------------------------------------------------------------------
__global__ __launch_bounds__(256) void k_split_w(const float* __restrict__ W,
                                                 const float* __restrict__ P) {
    int i = blockIdx.x * 256 + threadIdx.x;     // total 442368
    float v; __nv_bfloat16* base; int plane;
    if (i < C2_ * C_) { v = W[i]; base = g_Ws;  plane = C2_ * C_; }
    else { i -= C2_ * C_; v = P[i]; base = g_Pws; plane = C_ * C_; }
    __nv_bfloat16 b0 = __float2bfloat16(v);  v -= __bfloat162float(b0);
    __nv_bfloat16 b1 = __float2bfloat16(v);  v -= __bfloat162float(b1);
    __nv_bfloat16 b2 = __float2bfloat16(v);
    base[i] = b0; base[i + plane] = b1; base[i + 2 * plane] = b2;
}

// ---------------------------------------------------------------------------
// K2/K6: HMMA GEMM  D[m][n] = sum_{s,k} Wsplit_s[m][k] * Xspk[k][n], bn epilogue
//   mode 0 (gemm1): M=768, X=g_xsb; epilogue 3-splits into g_y1s/g_y2s
//   mode 1 (proj) : M=384, X=g_o1b; epilogue bn2 + residual -> out (fp32)
//   Block 128M x 64N, 8 warps (4m x 2n), warp 32x32. K chunks of 32, 3 splits.
// ---------------------------------------------------------------------------
#define WP_A 40
#define WP_B 72
__global__ __launch_bounds__(256) void k_wgemm(
    const float* __restrict__ gamma, const float* __restrict__ beta,
    const float* __restrict__ mean,  const float* __restrict__ var,
    const float* __restrict__ resid, float* __restrict__ outp,
    int M, int mode)
{
    const __nv_bfloat16* Wsrc = mode ? g_Pws : g_Ws;
    const __nv_bfloat16* X = (mode ? g_o1b : g_xsb) + (size_t)blockIdx.z * (C_ * L_);
    const int t2b = blockIdx.z;
    const int m0 = blockIdx.y * 128, n0 = blockIdx.x * 64;
    const int tid = threadIdx.x, lane = tid & 31, wid = tid >> 5;
    const int wm = wid & 3, wl = wid >> 2;

    __shared__ __nv_bfloat16 As[3 * 128 * WP_A];
    __shared__ __nv_bfloat16 Bs[32 * WP_B];
    const unsigned sA = smem_u32(As), sB = smem_u32(Bs);

    float acc[2][4][4] = {};
    const int a_r = wm * 32 + (lane & 15);                    // + mi*16
    const int a_c = (lane >> 4) * 8;                          // + kk*16
    const int b_r = (lane & 7) + ((lane >> 3) & 1) * 8;       // + kk*16
    const int b_c = wl * 32 + ((lane >> 4) & 1) * 8;          // + pair*16

    for (int kc = 0; kc < 12; ++kc) {
        const int k0 = kc * 32;
#pragma unroll
        for (int q = 0; q < 6; ++q) {                         // A: 3x128x4 uint4
            int id = tid + q * 256;
            int s = id >> 9, r = (id >> 2) & 127, c = id & 3;
            *(uint4*)&As[(s * 128 + r) * WP_A + c * 8] =
                *(const uint4*)(Wsrc + (size_t)s * M * C_ + (size_t)(m0 + r) * C_ + k0 + c * 8);
        }
        {                                                     // B: 32x8 uint4
            int r = tid >> 3, c = tid & 7;
            *(uint4*)&Bs[r * WP_B + c * 8] =
                *(const uint4*)(X + (size_t)(k0 + r) * L_ + n0 + c * 8);
        }
        __syncthreads();

        unsigned bfr[2][4][2];
#pragma unroll
        for (int kk = 0; kk < 2; ++kk)
#pragma unroll
            for (int pair = 0; pair < 2; ++pair) {
                unsigned bb[4];
                ldsm_x4t(bb, sB + 2u * ((kk * 16 + b_r) * WP_B + b_c + pair * 16));
                bfr[kk][pair * 2][0] = bb[0]; bfr[kk][pair * 2][1] = bb[1];
                bfr[kk][pair * 2 + 1][0] = bb[2]; bfr[kk][pair * 2 + 1][1] = bb[3];
            }
#pragma unroll
        for (int s = 0; s < 3; ++s)
#pragma unroll
            for (int kk = 0; kk < 2; ++kk) {
                unsigned a[2][4];
#pragma unroll
                for (int mi = 0; mi < 2; ++mi)
                    ldsm_x4(a[mi], sA + 2u * ((s * 128 + a_r + mi * 16) * WP_A + kk * 16 + a_c));
#pragma unroll
                for (int mi = 0; mi < 2; ++mi)
#pragma unroll
                    for (int ni = 0; ni < 4; ++ni)
                        mma16816(acc[mi][ni], a[mi], bfr[kk][ni]);
            }
        __syncthreads();
    }

    // Epilogue
    const int nb = n0 + wl * 32 + (lane & 3) * 2;
#pragma unroll
    for (int mi = 0; mi < 2; ++mi)
#pragma unroll
        for (int u = 0; u < 2; ++u) {
            int m = m0 + wm * 32 + mi * 16 + (lane >> 2) + u * 8;
            float inv = gamma[m] / sqrtf(var[m] + 1e-5f);
            float off = beta[m] - mean[m] * inv;
#pragma unroll
            for (int ni = 0; ni < 4; ++ni) {
                float v0 = acc[mi][ni][u * 2 + 0] * inv + off;
                float v1 = acc[mi][ni][u * 2 + 1] * inv + off;
                int n = nb + ni * 8;
                if (mode) {
                    const float2 rx = *(const float2*)(resid + (size_t)t2b * (C_ * L_) +
                                                       (size_t)m * L_ + n);
                    *(float2*)(outp + (size_t)t2b * (C_ * L_) + (size_t)m * L_ + n) =
                        make_float2(v0 + rx.x, v1 + rx.y);
                } else {
                    int hh = m / 96, rr = m % 96;
                    __nv_bfloat16* dst; size_t pb, st;
                    if (rr < 48) {
                        dst = g_y1s; st = 49152;
                        pb = ((size_t)(t2b * 8 + hh) * 3) * 49152 + (size_t)rr * 1024 + n;
                    } else {
                        dst = g_y2s; st = 65536;
                        pb = ((size_t)(t2b * 8 + hh) * 3) * 65536 + (size_t)(rr - 48) * 1024 + n;
                    }
#pragma unroll
                    for (int s = 0; s < 3; ++s) {
                        __nv_bfloat16 h0 = __float2bfloat16(v0); v0 -= __bfloat162float(h0);
                        __nv_bfloat16 h1 = __float2bfloat16(v1); v1 -= __bfloat162float(h1);
                        *(ushort2*)(dst + pb + (size_t)s * st) =
                            make_ushort2(bf_bits(h0), bf_bits(h1));
                    }
                }
            }
        }
}

// ---------------------------------------------------------------------------
// K3: HMMA attn  attnT[m][l] = sum_{s,d} xr[d][m] * y1s[s][d][l], fused t-scan
//   Block 128m x 64l, 8 warps (4m x 2l), warp 32x32. K=48 (3 k-steps), 3 splits.
//   Both operands loaded via ldmatrix.trans from natural d-major storage.
// ---------------------------------------------------------------------------
#define AP_A 136
#define AP_B 72
__global__ __launch_bounds__(256) void k_attn_mma() {
    const int bh = blockIdx.z, b = bh >> 3, h = bh & 7;
    const int m0 = blockIdx.y * 128, l0 = blockIdx.x * 64;
    const int tid = threadIdx.x, lane = tid & 31, wid = tid >> 5;
    const int wm = wid & 3, wl = wid >> 2;

    __shared__ __nv_bfloat16 As[48 * AP_A];        // xr [d][m-tile]
    __shared__ __nv_bfloat16 Bs[3 * 48 * AP_B];    // y1s [s][d][l-tile]
    const unsigned sA = smem_u32(As), sB = smem_u32(Bs);

    float mem[2][4][4];
#pragma unroll
    for (int i = 0; i < 2; ++i)
#pragma unroll
        for (int j = 0; j < 4; ++j)
#pragma unroll
            for (int q = 0; q < 4; ++q) mem[i][j][q] = 0.f;

    const int at_r = (lane & 7) + ((lane >> 4) & 1) * 8;   // d within k16
    const int at_c = wm * 32 + ((lane >> 3) & 1) * 8;      // m, + mi*16
    const int bt_r = (lane & 7) + ((lane >> 3) & 1) * 8;   // d within k16
    const int bt_c = wl * 32 + ((lane >> 4) & 1) * 8;      // l, + pair*16

    for (int t = 0; t < T_; ++t) {
        const int t2b = t * 2 + b;
        const __nv_bfloat16* xr = g_xsb + ((size_t)t2b * C_ + h * D_) * L_ + m0;
        const __nv_bfloat16* y1 = g_y1s + (size_t)(t2b * 8 + h) * 3 * 49152 + l0;
#pragma unroll
        for (int q = 0; q < 3; ++q) {                      // A: 48 rows x 16 uint4
            int id = tid + q * 256;
            int r = id >> 4, c = id & 15;
            *(uint4*)&As[r * AP_A + c * 8] = *(const uint4*)(xr + (size_t)r * L_ + c * 8);
        }
#pragma unroll
        for (int q = 0; q < 5; ++q) {                      // B: 144 rows x 8 uint4
            int id = tid + q * 256;
            if (id < 1152) {
                int sr = id >> 3, c = id & 7;
                *(uint4*)&Bs[sr * AP_B + c * 8] = *(const uint4*)(y1 + (size_t)sr * 1024 + c * 8);
            }
        }
        __syncthreads();

        unsigned a[3][2][4];
#pragma unroll
        for (int kk = 0; kk < 3; ++kk)
#pragma unroll
            for (int mi = 0; mi < 2; ++mi)
                ldsm_x4t(a[kk][mi], sA + 2u * ((kk * 16 + at_r) * AP_A + at_c + mi * 16));

        float acc[2][4][4] = {};
#pragma unroll
        for (int s = 0; s < 3; ++s)
#pragma unroll
            for (int kk = 0; kk < 3; ++kk) {
                unsigned bfr[4][2];
#pragma unroll
                for (int pair = 0; pair < 2; ++pair) {
                    unsigned bb[4];
                    ldsm_x4t(bb, sB + 2u * ((s * 48 + kk * 16 + bt_r) * AP_B + bt_c + pair * 16));
                    bfr[pair * 2][0] = bb[0]; bfr[pair * 2][1] = bb[1];
                    bfr[pair * 2 + 1][0] = bb[2]; bfr[pair * 2 + 1][1] = bb[3];
                }
#pragma unroll
                for (int mi = 0; mi < 2; ++mi)
#pragma unroll
                    for (int ni = 0; ni < 4; ++ni)
                        mma16816(acc[mi][ni], a[kk][mi], bfr[ni]);
            }

        // membrane update + spike store
        __nv_bfloat16* o = g_spkT + (size_t)(t * BH_ + bh) * LL;
#pragma unroll
        for (int mi = 0; mi < 2; ++mi)
#pragma unroll
            for (int u = 0; u < 2; ++u) {
                int m = m0 + wm * 32 + mi * 16 + (lane >> 2) + u * 8;
#pragma unroll
                for (int ni = 0; ni < 4; ++ni) {
                    float* mp = &mem[mi][ni][u * 2];
                    mp[0] = mp[0] * 0.25f * ((mp[0] > 0.5f) ? 0.f : 1.f) + acc[mi][ni][u * 2];
                    mp[1] = mp[1] * 0.25f * ((mp[1] > 0.5f) ? 0.f : 1.f) + acc[mi][ni][u * 2 + 1];
                    int l = l0 + wl * 32 + ni * 8 + (lane & 3) * 2;
                    *(ushort2*)(o + (size_t)m * L_ + l) =
                        make_ushort2(mp[0] > 0.5f ? 0x3F80 : 0, mp[1] > 0.5f ? 0x3F80 : 0);
                }
            }
        __syncthreads();
    }
}

// ---------------------------------------------------------------------------
// K4: HMMA GEMM  D[m][d] = sum_{s,l} spkT[m,l] * y2s[s][d][l]  (unchanged)
// ---------------------------------------------------------------------------
#define PAD_ 72
__global__ __launch_bounds__(256) void k_gemm2_mma() {
    const int z  = blockIdx.y;                 // t*16 + bh
    const int m0 = blockIdx.x * 128;
    const int t = z >> 4, bh = z & 15, b = bh >> 3, h = bh & 7;
    const int t2b = t * 2 + b;

    const int tid = threadIdx.x, lane = tid & 31, wid = tid >> 5;
    const int wm = wid & 3, wn = wid >> 2;

    __shared__ __nv_bfloat16 As[128 * PAD_];
    __shared__ __nv_bfloat16 Bs[144 * PAD_];

    const __nv_bfloat16* Ag = g_spkT + (size_t)z * LL + (size_t)m0 * L_;
    const __nv_bfloat16* Bg = g_y2s + (size_t)(t2b * 8 + h) * 3 * 65536;

    float acc[2][3][4] = {};
    const unsigned sA = smem_u32(As), sB = smem_u32(Bs);

    const int al_row  = wm * 32 + (lane & 15);
    const int al_coff = (lane >> 4) * 8;
    const int l4 = lane & 15;
    const int bl_row  = wn * 24 + (l4 & 7);
    const int bl_coff = (l4 >> 3) * 8;

    for (int it = 0; it < 16; ++it) {
        const int kt = it * 64;
        __syncthreads();
#pragma unroll
        for (int q = 0; q < 4; ++q) {
            int id = tid + q * 256, r = id >> 3, c = id & 7;
            *(uint4*)&As[r * PAD_ + c * 8] =
                *(const uint4*)(Ag + (size_t)r * L_ + kt + c * 8);
        }
#pragma unroll
        for (int q = 0; q < 5; ++q) {
            int id = tid + q * 256;
            if (id < 1152) {
                int s = id / 384, rr = (id % 384) >> 3, c = id & 7;
                *(uint4*)&Bs[(s * 48 + rr) * PAD_ + c * 8] =
                    *(const uint4*)(Bg + (size_t)s * 65536 + (size_t)rr * 1024 + kt + c * 8);
            }
        }
        __syncthreads();

        unsigned a[4][2][4];
#pragma unroll
        for (int kk = 0; kk < 4; ++kk)
#pragma unroll
            for (int mi = 0; mi < 2; ++mi)
                ldsm_x4(a[kk][mi],
                        sA + 2u * ((al_row + mi * 16) * PAD_ + kk * 16 + al_coff));
#pragma unroll
        for (int s = 0; s < 3; ++s) {
#pragma unroll
            for (int kk = 0; kk < 4; ++kk) {
                unsigned bf[3][2];
#pragma unroll
                for (int ni = 0; ni < 3; ++ni)
                    ldsm_x2(bf[ni],
                            sB + 2u * ((s * 48 + bl_row + ni * 8) * PAD_ + kk * 16 + bl_coff));
#pragma unroll
                for (int mi = 0; mi < 2; ++mi)
#pragma unroll
                    for (int ni = 0; ni < 3; ++ni)
                        mma16816(acc[mi][ni], a[kk][mi], bf[ni]);
            }
        }
    }

    float* O = g_o1 + (size_t)t2b * (C_ * L_) + (size_t)(h * D_) * L_;
    const int g = lane >> 2, tig = lane & 3;
#pragma unroll
    for (int mi = 0; mi < 2; ++mi) {
        int m = m0 + wm * 32 + mi * 16 + g;
#pragma unroll
        for (int ni = 0; ni < 3; ++ni) {
            int d0 = wn * 24 + ni * 8 + tig * 2;
            O[(size_t)d0 * L_ + m]           = acc[mi][ni][0];
            O[(size_t)(d0 + 1) * L_ + m]     = acc[mi][ni][1];
            O[(size_t)d0 * L_ + m + 8]       = acc[mi][ni][2];
            O[(size_t)(d0 + 1) * L_ + m + 8] = acc[mi][ni][3];
        }
    }
}

// ---------------------------------------------------------------------------
// K5: membrane scan over out1 -> bf16 spikes
// ---------------------------------------------------------------------------
__global__ __launch_bounds__(256) void k_scan_o1() {
    int i = blockIdx.x * 256 + threadIdx.x;
    if (i >= BCL) return;
    float mem = 0.f, sp = 0.f;
#pragma unroll
    for (int t = 0; t < T_; ++t) {
        mem = mem * 0.25f * (1.f - sp) + g_o1[(size_t)t * BCL + i];
        sp  = (mem > 0.5f) ? 1.f : 0.f;
        ((u16*)g_o1b)[(size_t)t * BCL + i] = (mem > 0.5f) ? 0x3F80 : 0;
    }
}

// ---------------------------------------------------------------------------
extern "C" void kernel_launch(void* const* d_in, const int* in_sizes, int n_in,
                              void* d_out, int out_size) {
    (void)in_sizes; (void)n_in; (void)out_size;
    const float* x   = (const float*)d_in[0];
    const float* W_w = (const float*)d_in[1];
    const float* g1  = (const float*)d_in[2];
    const float* be1 = (const float*)d_in[3];
    const float* me1 = (const float*)d_in[4];
    const float* v1  = (const float*)d_in[5];
    const float* pw  = (const float*)d_in[6];
    const float* g2  = (const float*)d_in[7];
    const float* be2 = (const float*)d_in[8];
    const float* me2 = (const float*)d_in[9];
    const float* v2  = (const float*)d_in[10];
    float* out = (float*)d_out;

    k_scan_x<<<BCL / 256, 256>>>(x);
    k_split_w<<<(C2_ * C_ + C_ * C_) / 256, 256>>>(W_w, pw);
    k_wgemm<<<dim3(L_ / 64, C2_ / 128, T_ * B_), 256>>>(
        g1, be1, me1, v1, nullptr, nullptr, C2_, 0);
    k_attn_mma<<<dim3(L_ / 64, L_ / 128, BH_), 256>>>();
    k_gemm2_mma<<<dim3(L_ / 128, T_ * BH_), 256>>>();
    k_scan_o1<<<BCL / 256, 256>>>();
    k_wgemm<<<dim3(L_ / 64, C_ / 128, T_ * B_), 256>>>(
        g2, be2, me2, v2, x, out, C_, 1);
}